// round 2
// baseline (speedup 1.0000x reference)
#include <cuda_runtime.h>
#include <cuda_bf16.h>
#include <math.h>

#define SEQ    512
#define BATCH  64
#define D_IN   1024
#define D_H    1024
#define M_IN   (SEQ * BATCH)      // 32768
#define BH     (BATCH * D_H)      // 65536
#define GRID_P 128                // persistent blocks (<=148 SMs -> all co-resident)
#define NB     8                  // columns per persistent block (128*8 = 1024)

// Persistent device scratch (allocation-free rule: __device__ globals).
__device__ float    g_hbuf[2][BH];   // double-buffered hidden state (2 x 256 KB)
__device__ unsigned g_count;         // monotonic grid-barrier counter

// ---------------------------------------------------------------------------
// init: hidden state <- h0, barrier counter <- 0
// ---------------------------------------------------------------------------
__global__ void init_h_kernel(const float* __restrict__ h0) {
    int idx = blockIdx.x * blockDim.x + threadIdx.x;
    if (idx < BH) g_hbuf[0][idx] = h0[idx];
    if (idx == 0) g_count = 0u;
}

// ---------------------------------------------------------------------------
// Input projection: out[m][n] = sum_i x[m][i]*Wih[n][i] + bih[n] + bhh[n]
// M=32768, N=1024, K=1024. BM=BN=128, BK=16, 8x8 thread tile, 256 threads.
// ---------------------------------------------------------------------------
__global__ __launch_bounds__(256) void input_gemm_kernel(
    const float* __restrict__ x, const float* __restrict__ Wih,
    const float* __restrict__ bih, const float* __restrict__ bhh,
    float* __restrict__ out)
{
    __shared__ __align__(16) float As[16][132];
    __shared__ __align__(16) float Bs[16][132];

    const int tid = threadIdx.x;
    const int m0 = blockIdx.y * 128;
    const int n0 = blockIdx.x * 128;
    const int tx = tid & 15;
    const int ty = tid >> 4;

    float acc[8][8];
    #pragma unroll
    for (int i = 0; i < 8; i++)
        #pragma unroll
        for (int j = 0; j < 8; j++) acc[i][j] = 0.0f;

    for (int k0 = 0; k0 < D_IN; k0 += 16) {
        #pragma unroll
        for (int l = 0; l < 2; l++) {
            int f = tid + l * 256;
            int r = f >> 2, c = (f & 3) * 4;
            float4 v = *(const float4*)(x + (size_t)(m0 + r) * D_IN + k0 + c);
            As[c + 0][r] = v.x; As[c + 1][r] = v.y;
            As[c + 2][r] = v.z; As[c + 3][r] = v.w;
        }
        #pragma unroll
        for (int l = 0; l < 2; l++) {
            int f = tid + l * 256;
            int r = f >> 2, c = (f & 3) * 4;
            float4 v = *(const float4*)(Wih + (size_t)(n0 + r) * D_IN + k0 + c);
            Bs[c + 0][r] = v.x; Bs[c + 1][r] = v.y;
            Bs[c + 2][r] = v.z; Bs[c + 3][r] = v.w;
        }
        __syncthreads();
        #pragma unroll
        for (int k = 0; k < 16; k++) {
            float a[8], b[8];
            *(float4*)&a[0] = *(const float4*)&As[k][ty * 8];
            *(float4*)&a[4] = *(const float4*)&As[k][ty * 8 + 4];
            *(float4*)&b[0] = *(const float4*)&Bs[k][tx * 8];
            *(float4*)&b[4] = *(const float4*)&Bs[k][tx * 8 + 4];
            #pragma unroll
            for (int i = 0; i < 8; i++)
                #pragma unroll
                for (int j = 0; j < 8; j++)
                    acc[i][j] += a[i] * b[j];
        }
        __syncthreads();
    }

    #pragma unroll
    for (int i = 0; i < 8; i++) {
        int m = m0 + ty * 8 + i;
        #pragma unroll
        for (int j = 0; j < 8; j += 4) {
            int n = n0 + tx * 8 + j;
            float4 o;
            o.x = acc[i][j + 0] + bih[n + 0] + bhh[n + 0];
            o.y = acc[i][j + 1] + bih[n + 1] + bhh[n + 1];
            o.z = acc[i][j + 2] + bih[n + 2] + bhh[n + 2];
            o.w = acc[i][j + 3] + bih[n + 3] + bhh[n + 3];
            *(float4*)(out + (size_t)m * D_H + n) = o;
        }
    }
}

// ---------------------------------------------------------------------------
// Persistent recurrence: all 512 steps in one kernel.
// Block bx owns columns j0 = bx*8. Whh slice [8 x 1024] cached in smem
// (bank-skewed). Thread t: b = t>>2, kc = t&3 (K-chunk of 256).
// Per step: partial dots -> shfl butterfly over kc -> tanh -> write
// out row + next h buffer -> grid barrier.
// ---------------------------------------------------------------------------
__global__ __launch_bounds__(256, 1) void rnn_persistent_kernel(
    const float* __restrict__ Whh, float* __restrict__ out, int write_tail)
{
    // skewed layout: idx(k,j) = k*8 + (k>>8)*4 + j  (breaks 4-way LDS conflicts)
    __shared__ __align__(16) float Ws[8 * 1024 + 16];

    const int tid = threadIdx.x;
    const int j0  = blockIdx.x * NB;
    const int b   = tid >> 2;        // 0..63
    const int kc  = tid & 3;         // K-chunk id
    const int kbase = kc << 8;       // kc*256

    // one-time Whh slice load (constant across all steps)
    #pragma unroll
    for (int j = 0; j < NB; j++) {
        int k = tid * 4;
        float4 v = *(const float4*)(Whh + (size_t)(j0 + j) * D_H + k);
        int sk = (k >> 8) << 2;
        Ws[(k + 0) * 8 + sk + j] = v.x;
        Ws[(k + 1) * 8 + sk + j] = v.y;
        Ws[(k + 2) * 8 + sk + j] = v.z;
        Ws[(k + 3) * 8 + sk + j] = v.w;
    }
    __syncthreads();

    const float* wbase = Ws + (kc << 2);   // fold skew (chunk-aligned: k>>8 == kc)

    for (int t = 0; t < SEQ; t++) {
        const float* hrow = g_hbuf[t & 1] + b * D_H + kbase;
        float*       hnew = g_hbuf[(t + 1) & 1] + b * D_H;

        float acc[8];
        #pragma unroll
        for (int j = 0; j < 8; j++) acc[j] = 0.0f;

        #pragma unroll 4
        for (int i = 0; i < 256; i += 8) {
            float hreg[8];
            float4 h0 = __ldcg((const float4*)(hrow + i));
            float4 h1 = __ldcg((const float4*)(hrow + i + 4));
            *(float4*)&hreg[0] = h0;
            *(float4*)&hreg[4] = h1;
            #pragma unroll
            for (int u = 0; u < 8; u++) {
                const float* wp = wbase + (size_t)(kbase + i + u) * 8;
                float4 w0 = *(const float4*)(wp);
                float4 w1 = *(const float4*)(wp + 4);
                float hk = hreg[u];
                acc[0] += hk * w0.x; acc[1] += hk * w0.y;
                acc[2] += hk * w0.z; acc[3] += hk * w0.w;
                acc[4] += hk * w1.x; acc[5] += hk * w1.y;
                acc[6] += hk * w1.z; acc[7] += hk * w1.w;
            }
        }

        // reduce over the 4 K-chunks (lanes differing in bits 0-1)
        #pragma unroll
        for (int j = 0; j < 8; j++) {
            acc[j] += __shfl_xor_sync(0xffffffffu, acc[j], 1);
            acc[j] += __shfl_xor_sync(0xffffffffu, acc[j], 2);
        }

        // lane kc finalizes columns j0 + kc*2, +1
        float s0, s1;
        if      (kc == 0) { s0 = acc[0]; s1 = acc[1]; }
        else if (kc == 1) { s0 = acc[2]; s1 = acc[3]; }
        else if (kc == 2) { s0 = acc[4]; s1 = acc[5]; }
        else              { s0 = acc[6]; s1 = acc[7]; }

        size_t ocol = (size_t)b * D_H + j0 + kc * 2;
        float* orow = out + (size_t)t * BH + ocol;
        float2 xp = *(const float2*)orow;          // xproj (+biases), private
        float2 hv;
        hv.x = tanhf(xp.x + s0);
        hv.y = tanhf(xp.y + s1);
        *(float2*)orow = hv;                       // output row (in place)
        __stcg((float2*)(hnew + j0 + kc * 2), hv); // next hidden state (L2)

        if (t == SEQ - 1 && write_tail) {
            *(float2*)(out + (size_t)SEQ * BH + ocol) = hv;
        }

        // grid barrier (skip after last step)
        if (t < SEQ - 1) {
            __threadfence();
            __syncthreads();
            if (tid == 0) {
                unsigned target = (unsigned)(t + 1) * GRID_P;
                atomicAdd(&g_count, 1u);
                while (*((volatile unsigned*)&g_count) < target) { }
            }
            __syncthreads();
        }
    }
}

extern "C" void kernel_launch(void* const* d_in, const int* in_sizes, int n_in,
                              void* d_out, int out_size) {
    const float* x   = (const float*)d_in[0];
    const float* h0  = (const float*)d_in[1];
    const float* Wih = (const float*)d_in[2];
    const float* bih = (const float*)d_in[3];
    const float* Whh = (const float*)d_in[4];
    const float* bhh = (const float*)d_in[5];
    float* out = (float*)d_out;

    init_h_kernel<<<(BH + 255) / 256, 256>>>(h0);

    input_gemm_kernel<<<dim3(D_H / 128, M_IN / 128), 256>>>(x, Wih, bih, bhh, out);

    long long total = (long long)SEQ * BH;
    int write_tail = ((long long)out_size >= total + BH) ? 1 : 0;
    rnn_persistent_kernel<<<GRID_P, 256>>>(Whh, out, write_tail);
}